// round 14
// baseline (speedup 1.0000x reference)
#include <cuda_runtime.h>
#include <cuda_fp16.h>

#define N_NODES_C 200000
#define N_EDGES_C 3200000
#define N_GRAPHS_C 1024
#define SCAN_B 256
#define MAX_BLOCKS_SCAN 1024

// ---------------- static device scratch (no allocs allowed) ----------------
__device__ __align__(16) float g_bufA[(size_t)N_NODES_C * 64];
__device__ __align__(16) float g_bufB[(size_t)N_NODES_C * 64];   // half h1 table (lower half)
__device__ __align__(16) float g_bufC[(size_t)N_NODES_C * 32];   // half t2 | half h3
__device__ __align__(16) float g_bufD[(size_t)N_NODES_C * 64];
__device__ __align__(16) int2  g_csr[N_EDGES_C];                 // {src, norm_bits}
__device__ __align__(16) int   g_deg[N_NODES_C];
__device__ __align__(16) int   g_incl[N_NODES_C];
__device__ __align__(16) int   g_rowstart[N_NODES_C];
__device__ __align__(16) int   g_cursor[N_NODES_C];
__device__ __align__(16) int   g_partials[MAX_BLOCKS_SCAN];
__device__ __align__(16) float g_dinv[N_NODES_C];
__device__ __align__(16) float g_gmax[N_GRAPHS_C * 32];
__device__ __align__(16) float g_gsum[N_GRAPHS_C * 32];
__device__ __align__(16) float g_gcnt[N_GRAPHS_C];

// ---------------- helpers ----------------
__device__ __forceinline__ void red_add_v4(float* addr, float4 v) {
    asm volatile("red.global.add.v4.f32 [%0], {%1, %2, %3, %4};"
                 :: "l"(addr), "f"(v.x), "f"(v.y), "f"(v.z), "f"(v.w)
                 : "memory");
}

__device__ __forceinline__ unsigned long long fma2(unsigned long long a,
                                                   unsigned long long b,
                                                   unsigned long long c) {
    unsigned long long d;
    asm("fma.rn.f32x2 %0, %1, %2, %3;" : "=l"(d) : "l"(a), "l"(b), "l"(c));
    return d;
}

__device__ __forceinline__ unsigned long long pack2(float x) {
    unsigned long long r;
    asm("mov.b64 %0, {%1, %1};" : "=l"(r) : "r"(__float_as_uint(x)));
    return r;
}

__device__ __forceinline__ float2 h2f(unsigned int u) {
    __half2 h = *reinterpret_cast<__half2*>(&u);
    return __half22float2(h);
}
__device__ __forceinline__ unsigned int f2h(float a, float b) {
    __half2 h = __floats2half2_rn(a, b);
    return *reinterpret_cast<unsigned int*>(&h);
}
__device__ __forceinline__ void fma8(float* acc, uint4 r, float n) {
    float2 p0 = h2f(r.x), p1 = h2f(r.y), p2 = h2f(r.z), p3 = h2f(r.w);
    acc[0] = fmaf(n, p0.x, acc[0]); acc[1] = fmaf(n, p0.y, acc[1]);
    acc[2] = fmaf(n, p1.x, acc[2]); acc[3] = fmaf(n, p1.y, acc[3]);
    acc[4] = fmaf(n, p2.x, acc[4]); acc[5] = fmaf(n, p2.y, acc[5]);
    acc[6] = fmaf(n, p3.x, acc[6]); acc[7] = fmaf(n, p3.y, acc[7]);
}

// ---------------- degree ----------------
__global__ void deg_kernel(const int* __restrict__ dst, int* __restrict__ deg, int E) {
    int t = blockIdx.x * blockDim.x + threadIdx.x;
    int e0 = t * 4;
    if (e0 >= E) return;
    if (e0 + 3 < E) {
        int4 d4 = *(const int4*)(dst + e0);
        atomicAdd(&deg[d4.x], 1);
        atomicAdd(&deg[d4.y], 1);
        atomicAdd(&deg[d4.z], 1);
        atomicAdd(&deg[d4.w], 1);
    } else {
        for (int k = 0; e0 + k < E; k++) atomicAdd(&deg[dst[e0 + k]], 1);
    }
}

__global__ void dinv_kernel(const int* __restrict__ deg, float* __restrict__ dinv, int N) {
    int i = blockIdx.x * blockDim.x + threadIdx.x;
    if (i < N) dinv[i] = rsqrtf((float)(deg[i] + 1));  // +1 self-loop
}

__global__ void init_small_kernel(float* __restrict__ gmax, float* __restrict__ gsum,
                                  float* __restrict__ gcnt) {
    int i = blockIdx.x * blockDim.x + threadIdx.x;
    if (i < N_GRAPHS_C * 32) { gmax[i] = 0.f; gsum[i] = 0.f; }
    if (i < N_GRAPHS_C) gcnt[i] = 0.f;
}

// ---------------- 3-phase exclusive scan of deg -> rowstart (+cursor copy) --------
__global__ void scan_block_kernel(const int* __restrict__ deg, int* __restrict__ incl,
                                  int* __restrict__ partials, int N) {
    __shared__ int sh[SCAN_B];
    int tid = threadIdx.x;
    int i = blockIdx.x * SCAN_B + tid;
    int v = (i < N) ? deg[i] : 0;
    sh[tid] = v;
    __syncthreads();
    #pragma unroll
    for (int off = 1; off < SCAN_B; off <<= 1) {
        int t = (tid >= off) ? sh[tid - off] : 0;
        __syncthreads();
        sh[tid] += t;
        __syncthreads();
    }
    if (i < N) incl[i] = sh[tid];
    if (tid == SCAN_B - 1) partials[blockIdx.x] = sh[tid];
}

__global__ void scan_partials_kernel(int* __restrict__ partials, int NB) {
    __shared__ int sh[MAX_BLOCKS_SCAN];
    int tid = threadIdx.x;
    sh[tid] = (tid < NB) ? partials[tid] : 0;
    __syncthreads();
    #pragma unroll
    for (int off = 1; off < MAX_BLOCKS_SCAN; off <<= 1) {
        int t = (tid >= off) ? sh[tid - off] : 0;
        __syncthreads();
        sh[tid] += t;
        __syncthreads();
    }
    if (tid < NB) partials[tid] = sh[tid];
}

__global__ void scan_final_kernel(const int* __restrict__ incl, const int* __restrict__ deg,
                                  const int* __restrict__ partials,
                                  int* __restrict__ rowstart, int* __restrict__ cursor, int N) {
    int i = blockIdx.x * SCAN_B + threadIdx.x;
    if (i >= N) return;
    int off = (blockIdx.x > 0) ? partials[blockIdx.x - 1] : 0;
    int rs = incl[i] - deg[i] + off;  // exclusive scan
    rowstart[i] = rs;
    cursor[i] = rs;
}

// ---------------- CSR fill: csr[pos] = {src, norm} grouped by dst ----------------
__global__ void fill_kernel(const int* __restrict__ src, const int* __restrict__ dst,
                            const float* __restrict__ dinv, int* __restrict__ cursor,
                            int2* __restrict__ csr, int E) {
    int e = blockIdx.x * blockDim.x + threadIdx.x;
    if (e >= E) return;
    int s = src[e];
    int d = dst[e];
    float nrm = dinv[s] * dinv[d];
    int pos = atomicAdd(&cursor[d], 1);
    csr[pos] = make_int2(s, __float_as_int(nrm));
}

// ---------------- warp-per-node fp32 gather (layer 0, C=8) ----------------
// lanes: j = lane&1 (float4 half-row), slot = lane>>1 (16 edge slots)
__global__ void gather0W_kernel(const float* __restrict__ t, float* __restrict__ agg,
                                const int2* __restrict__ csr, const int* __restrict__ rowstart,
                                const int* __restrict__ deg, const float* __restrict__ dinv, int N) {
    const int C = 8;
    int wid = (blockIdx.x * blockDim.x + threadIdx.x) >> 5;
    int lane = threadIdx.x & 31;
    if (wid >= N) return;
    int node = wid;
    int j = lane & 1;
    int slot = lane >> 1;
    const int SLOTS = 16;

    int start = rowstart[node];
    int cnt = deg[node];

    float4 acc = make_float4(0.f, 0.f, 0.f, 0.f);
    if (slot == 0) {
        float di = dinv[node];
        float s2 = di * di;
        float4 self = *(const float4*)(t + (size_t)node * C + j * 4);
        acc.x = s2 * self.x; acc.y = s2 * self.y;
        acc.z = s2 * self.z; acc.w = s2 * self.w;
    }

    int k = slot;
    for (; k + SLOTS < cnt; k += 2 * SLOTS) {
        int2 e0 = csr[start + k];
        int2 e1 = csr[start + k + SLOTS];
        float4 v0 = *(const float4*)(t + (size_t)e0.x * C + j * 4);
        float4 v1 = *(const float4*)(t + (size_t)e1.x * C + j * 4);
        float n0 = __int_as_float(e0.y);
        float n1 = __int_as_float(e1.y);
        acc.x = fmaf(n0, v0.x, acc.x); acc.y = fmaf(n0, v0.y, acc.y);
        acc.z = fmaf(n0, v0.z, acc.z); acc.w = fmaf(n0, v0.w, acc.w);
        acc.x = fmaf(n1, v1.x, acc.x); acc.y = fmaf(n1, v1.y, acc.y);
        acc.z = fmaf(n1, v1.z, acc.z); acc.w = fmaf(n1, v1.w, acc.w);
    }
    if (k < cnt) {
        int2 e0 = csr[start + k];
        float4 v0 = *(const float4*)(t + (size_t)e0.x * C + j * 4);
        float n0 = __int_as_float(e0.y);
        acc.x = fmaf(n0, v0.x, acc.x); acc.y = fmaf(n0, v0.y, acc.y);
        acc.z = fmaf(n0, v0.z, acc.z); acc.w = fmaf(n0, v0.w, acc.w);
    }

    #pragma unroll
    for (int off = 2; off < 32; off <<= 1) {
        acc.x += __shfl_xor_sync(0xffffffffu, acc.x, off);
        acc.y += __shfl_xor_sync(0xffffffffu, acc.y, off);
        acc.z += __shfl_xor_sync(0xffffffffu, acc.z, off);
        acc.w += __shfl_xor_sync(0xffffffffu, acc.w, off);
    }
    if (slot == 0) *(float4*)(agg + (size_t)node * C + j * 4) = acc;
}

// ---------------- warp-per-node half-input gather ----------------
// TPN = C/8 lanes per row (uint4 each), SLOTS = 32/TPN edge slots.
template<int C, bool ADDB, bool OUT_HALF_RELU>
__global__ void gatherW_kernel(const __half* __restrict__ t, void* __restrict__ outv,
                               const int2* __restrict__ csr, const int* __restrict__ rowstart,
                               const int* __restrict__ deg, const float* __restrict__ dinv,
                               const float* __restrict__ b, int N) {
    const int TPN = C / 8;
    const int SLOTS = 32 / TPN;
    int wid = (blockIdx.x * blockDim.x + threadIdx.x) >> 5;
    int lane = threadIdx.x & 31;
    if (wid >= N) return;
    int node = wid;
    int j = lane & (TPN - 1);
    int slot = lane / TPN;

    int start = rowstart[node];
    int cnt = deg[node];
    const uint4* tv = (const uint4*)t;

    float acc[8];
    #pragma unroll
    for (int i = 0; i < 8; i++) acc[i] = 0.f;
    if (slot == 0) {
        float di = dinv[node];
        float s2 = di * di;
        uint4 sv = tv[(size_t)node * TPN + j];
        float2 p0 = h2f(sv.x), p1 = h2f(sv.y), p2 = h2f(sv.z), p3 = h2f(sv.w);
        acc[0] = s2 * p0.x; acc[1] = s2 * p0.y;
        acc[2] = s2 * p1.x; acc[3] = s2 * p1.y;
        acc[4] = s2 * p2.x; acc[5] = s2 * p2.y;
        acc[6] = s2 * p3.x; acc[7] = s2 * p3.y;
        if (ADDB) {
            float4 b0 = *(const float4*)(b + j * 8);
            float4 b1 = *(const float4*)(b + j * 8 + 4);
            acc[0] += b0.x; acc[1] += b0.y; acc[2] += b0.z; acc[3] += b0.w;
            acc[4] += b1.x; acc[5] += b1.y; acc[6] += b1.z; acc[7] += b1.w;
        }
    }

    int k = slot;
    for (; k + SLOTS < cnt; k += 2 * SLOTS) {
        int2 e0 = csr[start + k];
        int2 e1 = csr[start + k + SLOTS];
        uint4 r0 = tv[(size_t)e0.x * TPN + j];
        uint4 r1 = tv[(size_t)e1.x * TPN + j];
        fma8(acc, r0, __int_as_float(e0.y));
        fma8(acc, r1, __int_as_float(e1.y));
    }
    if (k < cnt) {
        int2 e0 = csr[start + k];
        uint4 r0 = tv[(size_t)e0.x * TPN + j];
        fma8(acc, r0, __int_as_float(e0.y));
    }

    #pragma unroll
    for (int off = TPN; off < 32; off <<= 1) {
        #pragma unroll
        for (int i = 0; i < 8; i++)
            acc[i] += __shfl_xor_sync(0xffffffffu, acc[i], off);
    }

    if (slot == 0) {
        if (OUT_HALF_RELU) {
            #pragma unroll
            for (int i = 0; i < 8; i++) acc[i] = fmaxf(acc[i], 0.f);
            uint4 o;
            o.x = f2h(acc[0], acc[1]); o.y = f2h(acc[2], acc[3]);
            o.z = f2h(acc[4], acc[5]); o.w = f2h(acc[6], acc[7]);
            ((uint4*)outv)[(size_t)node * TPN + j] = o;
        } else {
            float* out = (float*)outv;
            *(float4*)(out + (size_t)node * C + j * 8)     = make_float4(acc[0], acc[1], acc[2], acc[3]);
            *(float4*)(out + (size_t)node * C + j * 8 + 4) = make_float4(acc[4], acc[5], acc[6], acc[7]);
        }
    }
}

// ---------------- GEMM: out[i] = act(in[i] @ W (+ b)); optional half output -------
// ACT: 0=none, 1=tanh, 2=relu.  in != out.
template<int IN, int OUT, int ACT, bool HASB, bool OUTH>
__global__ void gemm_kernel(const float* __restrict__ in, const float* __restrict__ W,
                            const float* __restrict__ b, void* __restrict__ outv, int N) {
    __shared__ __align__(16) float Ws[IN * OUT];
    __shared__ __align__(16) float bs[OUT];
    for (int i = threadIdx.x; i < IN * OUT; i += blockDim.x) Ws[i] = W[i];
    if (HASB) for (int i = threadIdx.x; i < OUT; i += blockDim.x) bs[i] = b[i];
    __syncthreads();

    int node = blockIdx.x * blockDim.x + threadIdx.x;
    if (node >= N) return;
    const float* row = in + (size_t)node * IN;

    unsigned long long acc[OUT / 2];
    #pragma unroll
    for (int j = 0; j < OUT / 2; j++) {
        if (HASB) {
            float2 bb = *(const float2*)&bs[2 * j];
            unsigned long long p;
            asm("mov.b64 %0, {%1, %2};" : "=l"(p)
                : "r"(__float_as_uint(bb.x)), "r"(__float_as_uint(bb.y)));
            acc[j] = p;
        } else {
            acc[j] = 0ULL;
        }
    }

    #pragma unroll 4
    for (int k = 0; k < IN; k++) {
        unsigned long long xk2 = pack2(row[k]);
        const unsigned long long* wrow = (const unsigned long long*)&Ws[k * OUT];
        #pragma unroll
        for (int j = 0; j < OUT / 2; j++)
            acc[j] = fma2(xk2, wrow[j], acc[j]);
    }

    float* o = OUTH ? nullptr : ((float*)outv + (size_t)node * OUT);
    unsigned int* oh = OUTH ? ((unsigned int*)outv + (size_t)node * (OUT / 2)) : nullptr;
    #pragma unroll
    for (int j = 0; j < OUT / 2; j++) {
        float2 v;
        unsigned int lo, hi;
        asm("mov.b64 {%0, %1}, %2;" : "=r"(lo), "=r"(hi) : "l"(acc[j]));
        v.x = __uint_as_float(lo); v.y = __uint_as_float(hi);
        if (ACT == 1) { v.x = tanhf(v.x); v.y = tanhf(v.y); }
        if (ACT == 2) { v.x = fmaxf(v.x, 0.f); v.y = fmaxf(v.y, 0.f); }
        if (OUTH) oh[j] = f2h(v.x, v.y);
        else      *(float2*)(o + 2 * j) = v;
    }
}

// ---------------- gemm3 (32->32 relu + bias) fused with pooling ----------------
__global__ void gemm3_pool_kernel(const float* __restrict__ in, const float* __restrict__ W,
                                  const float* __restrict__ b, const int* __restrict__ batch,
                                  float* __restrict__ gmax, float* __restrict__ gsum,
                                  float* __restrict__ gcnt, int N) {
    const int IN = 32, OUT = 32;
    __shared__ __align__(16) float Ws[IN * OUT];
    __shared__ __align__(16) float bs[OUT];
    for (int i = threadIdx.x; i < IN * OUT; i += blockDim.x) Ws[i] = W[i];
    for (int i = threadIdx.x; i < OUT; i += blockDim.x) bs[i] = b[i];
    __syncthreads();

    int node = blockIdx.x * blockDim.x + threadIdx.x;
    if (node >= N) return;
    const float* row = in + (size_t)node * IN;

    unsigned long long acc[OUT / 2];
    #pragma unroll
    for (int j = 0; j < OUT / 2; j++) {
        float2 bb = *(const float2*)&bs[2 * j];
        unsigned long long p;
        asm("mov.b64 %0, {%1, %2};" : "=l"(p)
            : "r"(__float_as_uint(bb.x)), "r"(__float_as_uint(bb.y)));
        acc[j] = p;
    }
    #pragma unroll 4
    for (int k = 0; k < IN; k++) {
        unsigned long long xk2 = pack2(row[k]);
        const unsigned long long* wrow = (const unsigned long long*)&Ws[k * OUT];
        #pragma unroll
        for (int j = 0; j < OUT / 2; j++)
            acc[j] = fma2(xk2, wrow[j], acc[j]);
    }

    float vals[OUT];
    #pragma unroll
    for (int j = 0; j < OUT / 2; j++) {
        unsigned int lo, hi;
        asm("mov.b64 {%0, %1}, %2;" : "=r"(lo), "=r"(hi) : "l"(acc[j]));
        vals[2 * j]     = fmaxf(__uint_as_float(lo), 0.f);
        vals[2 * j + 1] = fmaxf(__uint_as_float(hi), 0.f);
    }

    int g = batch[node];
    int base = g * 32;
    #pragma unroll
    for (int c = 0; c < OUT; c++)
        atomicMax((int*)gmax + base + c, __float_as_int(vals[c]));  // vals >= 0, gmax init 0
    #pragma unroll
    for (int q = 0; q < OUT / 4; q++)
        red_add_v4(gsum + base + q * 4,
                   make_float4(vals[4 * q], vals[4 * q + 1], vals[4 * q + 2], vals[4 * q + 3]));
    atomicAdd(&gcnt[g], 1.0f);
}

// ---------------- final linear ----------------
__global__ void out_kernel(const float* __restrict__ gmax, const float* __restrict__ gsum,
                           const float* __restrict__ gcnt, const float* __restrict__ Wout,
                           const float* __restrict__ bout, float* __restrict__ out) {
    int gid = blockIdx.x * blockDim.x + threadIdx.x;
    if (gid >= N_GRAPHS_C * 10) return;
    int g = gid / 10, o = gid % 10;
    float inv = 1.0f / fmaxf(gcnt[g], 1.0f);
    float acc = bout[o];
    #pragma unroll
    for (int k = 0; k < 32; k++) acc += gmax[g * 32 + k] * Wout[k * 10 + o];
    #pragma unroll
    for (int k = 0; k < 32; k++) acc += gsum[g * 32 + k] * inv * Wout[(32 + k) * 10 + o];
    out[gid] = acc;
}

// ---------------- launch ----------------
static inline int cdiv(long long a, int b) { return (int)((a + b - 1) / b); }

extern "C" void kernel_launch(void* const* d_in, const int* in_sizes, int n_in,
                              void* d_out, int out_size) {
    const float* x     = (const float*)d_in[0];
    const int*   ei    = (const int*)d_in[1];    // int32 (JAX x64 disabled)
    const int*   batch = (const int*)d_in[2];    // int32
    const float* W0 = (const float*)d_in[3];
    const float* b0 = (const float*)d_in[4];
    const float* W1 = (const float*)d_in[5];
    const float* b1 = (const float*)d_in[6];
    const float* W2 = (const float*)d_in[7];
    const float* b2 = (const float*)d_in[8];
    const float* W3 = (const float*)d_in[9];
    const float* b3 = (const float*)d_in[10];
    const float* Wout = (const float*)d_in[11];
    const float* bout = (const float*)d_in[12];

    int N = in_sizes[0] / 8;
    int E = in_sizes[1] / 2;
    const int* src = ei;
    const int* dst = ei + E;

    float *bufA, *bufB, *bufC, *bufD, *dinv, *gmax, *gsum, *gcnt;
    int *deg, *incl, *rowstart, *cursor, *partials; int2 *csr;
    cudaGetSymbolAddress((void**)&bufA, g_bufA);
    cudaGetSymbolAddress((void**)&bufB, g_bufB);
    cudaGetSymbolAddress((void**)&bufC, g_bufC);
    cudaGetSymbolAddress((void**)&bufD, g_bufD);
    cudaGetSymbolAddress((void**)&csr,  g_csr);
    cudaGetSymbolAddress((void**)&deg,  g_deg);
    cudaGetSymbolAddress((void**)&incl, g_incl);
    cudaGetSymbolAddress((void**)&rowstart, g_rowstart);
    cudaGetSymbolAddress((void**)&cursor,   g_cursor);
    cudaGetSymbolAddress((void**)&partials, g_partials);
    cudaGetSymbolAddress((void**)&dinv, g_dinv);
    cudaGetSymbolAddress((void**)&gmax, g_gmax);
    cudaGetSymbolAddress((void**)&gsum, g_gsum);
    cudaGetSymbolAddress((void**)&gcnt, g_gcnt);

    // half-table views
    __half* h1h = (__half*)bufB;                              // 200k x 64 halves
    __half* t2h = (__half*)bufC;                              // 200k x 32 halves
    __half* h3h = (__half*)bufC + (size_t)N_NODES_C * 32;     // 200k x 32 halves

    const int B = 256;
    int NB = cdiv(N, SCAN_B);  // 782 <= 1024

    cudaMemsetAsync(deg, 0, (size_t)N * sizeof(int));
    init_small_kernel<<<cdiv(N_GRAPHS_C * 32, B), B>>>(gmax, gsum, gcnt);

    // ---- graph preprocessing: deg, dinv, CSR ----
    deg_kernel<<<cdiv(cdiv(E, 4), B), B>>>(dst, deg, E);
    dinv_kernel<<<cdiv(N, B), B>>>(deg, dinv, N);
    scan_block_kernel<<<NB, SCAN_B>>>(deg, incl, partials, N);
    scan_partials_kernel<<<1, MAX_BLOCKS_SCAN>>>(partials, NB);
    scan_final_kernel<<<NB, SCAN_B>>>(incl, deg, partials, rowstart, cursor, N);
    fill_kernel<<<cdiv(E, B), B>>>(src, dst, dinv, cursor, csr, E);

    // ---- layer 0: warp-per-node gather C=8 fp32, then 8->64 tanh -> half h1 ----
    gather0W_kernel<<<cdiv((long long)N * 32, B), B>>>(x, bufA, csr, rowstart, deg, dinv, N);
    gemm_kernel<8, 64, 1, true, true><<<cdiv(N, B), B>>>(bufA, W0, b0, h1h, N);

    // ---- layer 1: warp-per-node half gather C=64 -> fp32, 64->64 relu ----
    gatherW_kernel<64, false, false><<<cdiv((long long)N * 32, B), B>>>(h1h, bufD, csr, rowstart, deg, dinv, nullptr, N);
    gemm_kernel<64, 64, 2, true, false><<<cdiv(N, B), B>>>(bufD, W1, b1, bufA, N);

    // ---- layer 2: GEMM first (64->32) -> half t2; gather(+b2, relu) -> half h3 ----
    gemm_kernel<64, 32, 0, false, true><<<cdiv(N, B), B>>>(bufA, W2, nullptr, t2h, N);
    gatherW_kernel<32, true, true><<<cdiv((long long)N * 32, B), B>>>(t2h, h3h, csr, rowstart, deg, dinv, b2, N);

    // ---- layer 3: half gather C=32 -> fp32, then fused 32->32 relu GEMM + pooling ----
    gatherW_kernel<32, false, false><<<cdiv((long long)N * 32, B), B>>>(h3h, bufD, csr, rowstart, deg, dinv, nullptr, N);
    gemm3_pool_kernel<<<cdiv(N, B), B>>>(bufD, W3, b3, batch, gmax, gsum, gcnt, N);

    // ---- output head ----
    out_kernel<<<cdiv(N_GRAPHS_C * 10, B), B>>>(gmax, gsum, gcnt, Wout, bout, (float*)d_out);
}

// round 16
// speedup vs baseline: 1.2139x; 1.2139x over previous
#include <cuda_runtime.h>
#include <cuda_fp16.h>

#define N_NODES_C 200000
#define N_EDGES_C 3200000
#define N_GRAPHS_C 1024
#define SCAN_B 256
#define MAX_BLOCKS_SCAN 1024

// ---------------- static device scratch (no allocs allowed) ----------------
__device__ __align__(16) float g_bufA[(size_t)N_NODES_C * 64];   // x' half | h2 fp32
__device__ __align__(16) float g_bufB[(size_t)N_NODES_C * 64];   // h1' half table
__device__ __align__(16) float g_bufC[(size_t)N_NODES_C * 32];   // t2' half | h3' half
__device__ __align__(16) float g_bufD[(size_t)N_NODES_C * 64];   // fp32 agg staging
__device__ __align__(16) int   g_csr[N_EDGES_C];                 // src only (table pre-scaled)
__device__ __align__(16) int   g_deg[N_NODES_C];
__device__ __align__(16) int   g_incl[N_NODES_C];
__device__ __align__(16) int   g_rowstart[N_NODES_C];
__device__ __align__(16) int   g_cursor[N_NODES_C];
__device__ __align__(16) int   g_partials[MAX_BLOCKS_SCAN];
__device__ __align__(16) float g_dinv[N_NODES_C];
__device__ __align__(16) float g_gmax[N_GRAPHS_C * 32];
__device__ __align__(16) float g_gsum[N_GRAPHS_C * 32];
__device__ __align__(16) float g_gcnt[N_GRAPHS_C];

// ---------------- helpers ----------------
__device__ __forceinline__ void red_add_v4(float* addr, float4 v) {
    asm volatile("red.global.add.v4.f32 [%0], {%1, %2, %3, %4};"
                 :: "l"(addr), "f"(v.x), "f"(v.y), "f"(v.z), "f"(v.w)
                 : "memory");
}

__device__ __forceinline__ unsigned long long fma2(unsigned long long a,
                                                   unsigned long long b,
                                                   unsigned long long c) {
    unsigned long long d;
    asm("fma.rn.f32x2 %0, %1, %2, %3;" : "=l"(d) : "l"(a), "l"(b), "l"(c));
    return d;
}

__device__ __forceinline__ unsigned long long pack2(float x) {
    unsigned long long r;
    asm("mov.b64 %0, {%1, %1};" : "=l"(r) : "r"(__float_as_uint(x)));
    return r;
}

__device__ __forceinline__ float2 h2f(unsigned int u) {
    __half2 h = *reinterpret_cast<__half2*>(&u);
    return __half22float2(h);
}
__device__ __forceinline__ unsigned int f2h(float a, float b) {
    __half2 h = __floats2half2_rn(a, b);
    return *reinterpret_cast<unsigned int*>(&h);
}
__device__ __forceinline__ void add8(float* acc, uint4 r) {
    float2 p0 = h2f(r.x), p1 = h2f(r.y), p2 = h2f(r.z), p3 = h2f(r.w);
    acc[0] += p0.x; acc[1] += p0.y;
    acc[2] += p1.x; acc[3] += p1.y;
    acc[4] += p2.x; acc[5] += p2.y;
    acc[6] += p3.x; acc[7] += p3.y;
}

// ---------------- degree ----------------
__global__ void deg_kernel(const int* __restrict__ dst, int* __restrict__ deg, int E) {
    int t = blockIdx.x * blockDim.x + threadIdx.x;
    int e0 = t * 4;
    if (e0 >= E) return;
    if (e0 + 3 < E) {
        int4 d4 = *(const int4*)(dst + e0);
        atomicAdd(&deg[d4.x], 1);
        atomicAdd(&deg[d4.y], 1);
        atomicAdd(&deg[d4.z], 1);
        atomicAdd(&deg[d4.w], 1);
    } else {
        for (int k = 0; e0 + k < E; k++) atomicAdd(&deg[dst[e0 + k]], 1);
    }
}

__global__ void dinv_kernel(const int* __restrict__ deg, float* __restrict__ dinv, int N) {
    int i = blockIdx.x * blockDim.x + threadIdx.x;
    if (i < N) dinv[i] = rsqrtf((float)(deg[i] + 1));  // +1 self-loop
}

__global__ void init_small_kernel(float* __restrict__ gmax, float* __restrict__ gsum,
                                  float* __restrict__ gcnt) {
    int i = blockIdx.x * blockDim.x + threadIdx.x;
    if (i < N_GRAPHS_C * 32) { gmax[i] = 0.f; gsum[i] = 0.f; }
    if (i < N_GRAPHS_C) gcnt[i] = 0.f;
}

// ---------------- 3-phase exclusive scan of deg -> rowstart (+cursor copy) --------
__global__ void scan_block_kernel(const int* __restrict__ deg, int* __restrict__ incl,
                                  int* __restrict__ partials, int N) {
    __shared__ int sh[SCAN_B];
    int tid = threadIdx.x;
    int i = blockIdx.x * SCAN_B + tid;
    int v = (i < N) ? deg[i] : 0;
    sh[tid] = v;
    __syncthreads();
    #pragma unroll
    for (int off = 1; off < SCAN_B; off <<= 1) {
        int t = (tid >= off) ? sh[tid - off] : 0;
        __syncthreads();
        sh[tid] += t;
        __syncthreads();
    }
    if (i < N) incl[i] = sh[tid];
    if (tid == SCAN_B - 1) partials[blockIdx.x] = sh[tid];
}

__global__ void scan_partials_kernel(int* __restrict__ partials, int NB) {
    __shared__ int sh[MAX_BLOCKS_SCAN];
    int tid = threadIdx.x;
    sh[tid] = (tid < NB) ? partials[tid] : 0;
    __syncthreads();
    #pragma unroll
    for (int off = 1; off < MAX_BLOCKS_SCAN; off <<= 1) {
        int t = (tid >= off) ? sh[tid - off] : 0;
        __syncthreads();
        sh[tid] += t;
        __syncthreads();
    }
    if (tid < NB) partials[tid] = sh[tid];
}

__global__ void scan_final_kernel(const int* __restrict__ incl, const int* __restrict__ deg,
                                  const int* __restrict__ partials,
                                  int* __restrict__ rowstart, int* __restrict__ cursor, int N) {
    int i = blockIdx.x * SCAN_B + threadIdx.x;
    if (i >= N) return;
    int off = (blockIdx.x > 0) ? partials[blockIdx.x - 1] : 0;
    int rs = incl[i] - deg[i] + off;  // exclusive scan
    rowstart[i] = rs;
    cursor[i] = rs;
}

// ---------------- CSR fill: csr[pos] = src, grouped by dst (no norms needed) ------
__global__ void fill_kernel(const int* __restrict__ src, const int* __restrict__ dst,
                            int* __restrict__ cursor, int* __restrict__ csr, int E) {
    int t = blockIdx.x * blockDim.x + threadIdx.x;
    int e0 = t * 4;
    if (e0 >= E) return;
    if (e0 + 3 < E) {
        int4 s4 = *(const int4*)(src + e0);
        int4 d4 = *(const int4*)(dst + e0);
        csr[atomicAdd(&cursor[d4.x], 1)] = s4.x;
        csr[atomicAdd(&cursor[d4.y], 1)] = s4.y;
        csr[atomicAdd(&cursor[d4.z], 1)] = s4.z;
        csr[atomicAdd(&cursor[d4.w], 1)] = s4.w;
    } else {
        for (int k = 0; e0 + k < E; k++)
            csr[atomicAdd(&cursor[dst[e0 + k]], 1)] = src[e0 + k];
    }
}

// ---------------- build x' = dinv * x as half table ----------------
__global__ void xscale_kernel(const float* __restrict__ x, const float* __restrict__ dinv,
                              uint4* __restrict__ xh, int N) {
    int i = blockIdx.x * blockDim.x + threadIdx.x;
    if (i >= N) return;
    float di = dinv[i];
    float4 v0 = *(const float4*)(x + (size_t)i * 8);
    float4 v1 = *(const float4*)(x + (size_t)i * 8 + 4);
    uint4 o;
    o.x = f2h(di * v0.x, di * v0.y);
    o.y = f2h(di * v0.z, di * v0.w);
    o.z = f2h(di * v1.x, di * v1.y);
    o.w = f2h(di * v1.z, di * v1.w);
    xh[i] = o;
}

// ---------------- gather on pre-scaled half table, chunk-parallel -----------------
// acc_raw = sum_e t[src_e] + t[node];  agg = dinv[node]*acc_raw (+ b)
// OUT_HALF_RELU: out = half( dinv[node] * relu(agg) )   else: out = fp32 agg
template<int C, bool ADDB, bool OUT_HALF_RELU>
__global__ void gatherS_kernel(const uint4* __restrict__ tv, void* __restrict__ outv,
                               const int* __restrict__ csr, const int* __restrict__ rowstart,
                               const int* __restrict__ deg, const float* __restrict__ dinv,
                               const float* __restrict__ b, int N) {
    const int TPN = C / 8;   // one uint4 (8 halves) per lane
    int gid = blockIdx.x * blockDim.x + threadIdx.x;
    int node = (TPN == 1) ? gid : gid / TPN;
    int j = (TPN == 1) ? 0 : (gid % TPN);
    if (node >= N) return;

    int start = rowstart[node];
    int cnt = deg[node];
    float di = dinv[node];

    float acc[8];
    {
        // self term: just another row of the pre-scaled table
        uint4 sv = tv[(size_t)node * TPN + j];
        float2 p0 = h2f(sv.x), p1 = h2f(sv.y), p2 = h2f(sv.z), p3 = h2f(sv.w);
        acc[0] = p0.x; acc[1] = p0.y; acc[2] = p1.x; acc[3] = p1.y;
        acc[4] = p2.x; acc[5] = p2.y; acc[6] = p3.x; acc[7] = p3.y;
    }

    int k = 0;
    for (; k + 4 <= cnt; k += 4) {
        int s0 = csr[start + k];
        int s1 = csr[start + k + 1];
        int s2 = csr[start + k + 2];
        int s3 = csr[start + k + 3];
        uint4 r0 = tv[(size_t)s0 * TPN + j];
        uint4 r1 = tv[(size_t)s1 * TPN + j];
        uint4 r2 = tv[(size_t)s2 * TPN + j];
        uint4 r3 = tv[(size_t)s3 * TPN + j];
        add8(acc, r0); add8(acc, r1); add8(acc, r2); add8(acc, r3);
    }
    for (; k < cnt; k++) {
        int s0 = csr[start + k];
        add8(acc, tv[(size_t)s0 * TPN + j]);
    }

    #pragma unroll
    for (int i = 0; i < 8; i++) acc[i] *= di;
    if (ADDB) {
        float4 b0 = *(const float4*)(b + j * 8);
        float4 b1 = *(const float4*)(b + j * 8 + 4);
        acc[0] += b0.x; acc[1] += b0.y; acc[2] += b0.z; acc[3] += b0.w;
        acc[4] += b1.x; acc[5] += b1.y; acc[6] += b1.z; acc[7] += b1.w;
    }

    if (OUT_HALF_RELU) {
        #pragma unroll
        for (int i = 0; i < 8; i++) acc[i] = di * fmaxf(acc[i], 0.f);  // next layer's scaled table
        uint4 o;
        o.x = f2h(acc[0], acc[1]); o.y = f2h(acc[2], acc[3]);
        o.z = f2h(acc[4], acc[5]); o.w = f2h(acc[6], acc[7]);
        ((uint4*)outv)[(size_t)node * TPN + j] = o;
    } else {
        float* out = (float*)outv;
        *(float4*)(out + (size_t)node * C + j * 8)     = make_float4(acc[0], acc[1], acc[2], acc[3]);
        *(float4*)(out + (size_t)node * C + j * 8 + 4) = make_float4(acc[4], acc[5], acc[6], acc[7]);
    }
}

// ---------------- GEMM: out[i] = act(in[i] @ W (+ b)) -----------------------------
// ACT: 0=none, 1=tanh, 2=relu.  OUTH: write half, scaled by dinv[node] (table output)
template<int IN, int OUT, int ACT, bool HASB, bool OUTH>
__global__ void gemm_kernel(const float* __restrict__ in, const float* __restrict__ W,
                            const float* __restrict__ b, void* __restrict__ outv,
                            const float* __restrict__ dinv, int N) {
    __shared__ __align__(16) float Ws[IN * OUT];
    __shared__ __align__(16) float bs[OUT];
    for (int i = threadIdx.x; i < IN * OUT; i += blockDim.x) Ws[i] = W[i];
    if (HASB) for (int i = threadIdx.x; i < OUT; i += blockDim.x) bs[i] = b[i];
    __syncthreads();

    int node = blockIdx.x * blockDim.x + threadIdx.x;
    if (node >= N) return;
    const float* row = in + (size_t)node * IN;

    unsigned long long acc[OUT / 2];
    #pragma unroll
    for (int j = 0; j < OUT / 2; j++) {
        if (HASB) {
            float2 bb = *(const float2*)&bs[2 * j];
            unsigned long long p;
            asm("mov.b64 %0, {%1, %2};" : "=l"(p)
                : "r"(__float_as_uint(bb.x)), "r"(__float_as_uint(bb.y)));
            acc[j] = p;
        } else {
            acc[j] = 0ULL;
        }
    }

    #pragma unroll 4
    for (int k = 0; k < IN; k++) {
        unsigned long long xk2 = pack2(row[k]);
        const unsigned long long* wrow = (const unsigned long long*)&Ws[k * OUT];
        #pragma unroll
        for (int j = 0; j < OUT / 2; j++)
            acc[j] = fma2(xk2, wrow[j], acc[j]);
    }

    float di = OUTH ? dinv[node] : 0.f;
    float* o = OUTH ? nullptr : ((float*)outv + (size_t)node * OUT);
    unsigned int* oh = OUTH ? ((unsigned int*)outv + (size_t)node * (OUT / 2)) : nullptr;
    #pragma unroll
    for (int j = 0; j < OUT / 2; j++) {
        float2 v;
        unsigned int lo, hi;
        asm("mov.b64 {%0, %1}, %2;" : "=r"(lo), "=r"(hi) : "l"(acc[j]));
        v.x = __uint_as_float(lo); v.y = __uint_as_float(hi);
        if (ACT == 1) { v.x = tanhf(v.x); v.y = tanhf(v.y); }
        if (ACT == 2) { v.x = fmaxf(v.x, 0.f); v.y = fmaxf(v.y, 0.f); }
        if (OUTH) oh[j] = f2h(di * v.x, di * v.y);
        else      *(float2*)(o + 2 * j) = v;
    }
}

// ---------------- gemm3 (32->32 relu + bias) fused with pooling ----------------
__global__ void gemm3_pool_kernel(const float* __restrict__ in, const float* __restrict__ W,
                                  const float* __restrict__ b, const int* __restrict__ batch,
                                  float* __restrict__ gmax, float* __restrict__ gsum,
                                  float* __restrict__ gcnt, int N) {
    const int IN = 32, OUT = 32;
    __shared__ __align__(16) float Ws[IN * OUT];
    __shared__ __align__(16) float bs[OUT];
    for (int i = threadIdx.x; i < IN * OUT; i += blockDim.x) Ws[i] = W[i];
    for (int i = threadIdx.x; i < OUT; i += blockDim.x) bs[i] = b[i];
    __syncthreads();

    int node = blockIdx.x * blockDim.x + threadIdx.x;
    if (node >= N) return;
    const float* row = in + (size_t)node * IN;

    unsigned long long acc[OUT / 2];
    #pragma unroll
    for (int j = 0; j < OUT / 2; j++) {
        float2 bb = *(const float2*)&bs[2 * j];
        unsigned long long p;
        asm("mov.b64 %0, {%1, %2};" : "=l"(p)
            : "r"(__float_as_uint(bb.x)), "r"(__float_as_uint(bb.y)));
        acc[j] = p;
    }
    #pragma unroll 4
    for (int k = 0; k < IN; k++) {
        unsigned long long xk2 = pack2(row[k]);
        const unsigned long long* wrow = (const unsigned long long*)&Ws[k * OUT];
        #pragma unroll
        for (int j = 0; j < OUT / 2; j++)
            acc[j] = fma2(xk2, wrow[j], acc[j]);
    }

    float vals[OUT];
    #pragma unroll
    for (int j = 0; j < OUT / 2; j++) {
        unsigned int lo, hi;
        asm("mov.b64 {%0, %1}, %2;" : "=r"(lo), "=r"(hi) : "l"(acc[j]));
        vals[2 * j]     = fmaxf(__uint_as_float(lo), 0.f);
        vals[2 * j + 1] = fmaxf(__uint_as_float(hi), 0.f);
    }

    int g = batch[node];
    int base = g * 32;
    #pragma unroll
    for (int c = 0; c < OUT; c++)
        atomicMax((int*)gmax + base + c, __float_as_int(vals[c]));  // vals >= 0, gmax init 0
    #pragma unroll
    for (int q = 0; q < OUT / 4; q++)
        red_add_v4(gsum + base + q * 4,
                   make_float4(vals[4 * q], vals[4 * q + 1], vals[4 * q + 2], vals[4 * q + 3]));
    atomicAdd(&gcnt[g], 1.0f);
}

// ---------------- final linear ----------------
__global__ void out_kernel(const float* __restrict__ gmax, const float* __restrict__ gsum,
                           const float* __restrict__ gcnt, const float* __restrict__ Wout,
                           const float* __restrict__ bout, float* __restrict__ out) {
    int gid = blockIdx.x * blockDim.x + threadIdx.x;
    if (gid >= N_GRAPHS_C * 10) return;
    int g = gid / 10, o = gid % 10;
    float inv = 1.0f / fmaxf(gcnt[g], 1.0f);
    float acc = bout[o];
    #pragma unroll
    for (int k = 0; k < 32; k++) acc += gmax[g * 32 + k] * Wout[k * 10 + o];
    #pragma unroll
    for (int k = 0; k < 32; k++) acc += gsum[g * 32 + k] * inv * Wout[(32 + k) * 10 + o];
    out[gid] = acc;
}

// ---------------- launch ----------------
static inline int cdiv(long long a, int b) { return (int)((a + b - 1) / b); }

extern "C" void kernel_launch(void* const* d_in, const int* in_sizes, int n_in,
                              void* d_out, int out_size) {
    const float* x     = (const float*)d_in[0];
    const int*   ei    = (const int*)d_in[1];    // int32 (JAX x64 disabled)
    const int*   batch = (const int*)d_in[2];    // int32
    const float* W0 = (const float*)d_in[3];
    const float* b0 = (const float*)d_in[4];
    const float* W1 = (const float*)d_in[5];
    const float* b1 = (const float*)d_in[6];
    const float* W2 = (const float*)d_in[7];
    const float* b2 = (const float*)d_in[8];
    const float* W3 = (const float*)d_in[9];
    const float* b3 = (const float*)d_in[10];
    const float* Wout = (const float*)d_in[11];
    const float* bout = (const float*)d_in[12];

    int N = in_sizes[0] / 8;
    int E = in_sizes[1] / 2;
    const int* src = ei;
    const int* dst = ei + E;

    float *bufA, *bufB, *bufC, *bufD, *dinv, *gmax, *gsum, *gcnt;
    int *csr, *deg, *incl, *rowstart, *cursor, *partials;
    cudaGetSymbolAddress((void**)&bufA, g_bufA);
    cudaGetSymbolAddress((void**)&bufB, g_bufB);
    cudaGetSymbolAddress((void**)&bufC, g_bufC);
    cudaGetSymbolAddress((void**)&bufD, g_bufD);
    cudaGetSymbolAddress((void**)&csr,  g_csr);
    cudaGetSymbolAddress((void**)&deg,  g_deg);
    cudaGetSymbolAddress((void**)&incl, g_incl);
    cudaGetSymbolAddress((void**)&rowstart, g_rowstart);
    cudaGetSymbolAddress((void**)&cursor,   g_cursor);
    cudaGetSymbolAddress((void**)&partials, g_partials);
    cudaGetSymbolAddress((void**)&dinv, g_dinv);
    cudaGetSymbolAddress((void**)&gmax, g_gmax);
    cudaGetSymbolAddress((void**)&gsum, g_gsum);
    cudaGetSymbolAddress((void**)&gcnt, g_gcnt);

    // half-table views (each table pre-scaled by dinv)
    uint4* xh  = (uint4*)bufA;                                  // 200k x 8 halves
    uint4* h1h = (uint4*)bufB;                                  // 200k x 64 halves
    uint4* t2h = (uint4*)bufC;                                  // 200k x 32 halves
    uint4* h3h = (uint4*)((__half*)bufC + (size_t)N_NODES_C * 32);  // 200k x 32 halves

    const int B = 256;
    int NB = cdiv(N, SCAN_B);  // 782 <= 1024

    cudaMemsetAsync(deg, 0, (size_t)N * sizeof(int));
    init_small_kernel<<<cdiv(N_GRAPHS_C * 32, B), B>>>(gmax, gsum, gcnt);

    // ---- graph preprocessing: deg, dinv, CSR (src-only) ----
    deg_kernel<<<cdiv(cdiv(E, 4), B), B>>>(dst, deg, E);
    dinv_kernel<<<cdiv(N, B), B>>>(deg, dinv, N);
    scan_block_kernel<<<NB, SCAN_B>>>(deg, incl, partials, N);
    scan_partials_kernel<<<1, MAX_BLOCKS_SCAN>>>(partials, NB);
    scan_final_kernel<<<NB, SCAN_B>>>(incl, deg, partials, rowstart, cursor, N);
    fill_kernel<<<cdiv(cdiv(E, 4), B), B>>>(src, dst, cursor, csr, E);

    // ---- layer 0: x' = dinv*x (half); gather C=8; 8->64 tanh -> scaled half h1' ----
    xscale_kernel<<<cdiv(N, B), B>>>(x, dinv, xh, N);
    gatherS_kernel<8, false, false><<<cdiv(N, B), B>>>(xh, bufD, csr, rowstart, deg, dinv, nullptr, N);
    gemm_kernel<8, 64, 1, true, true><<<cdiv(N, B), B>>>(bufD, W0, b0, h1h, dinv, N);

    // ---- layer 1: gather C=64 -> fp32 agg1; 64->64 relu -> fp32 h2 ----
    gatherS_kernel<64, false, false><<<cdiv((long long)N * 8, B), B>>>(h1h, bufD, csr, rowstart, deg, dinv, nullptr, N);
    gemm_kernel<64, 64, 2, true, false><<<cdiv(N, B), B>>>(bufD, W1, b1, bufA, nullptr, N);

    // ---- layer 2: 64->32 (no act) -> scaled half t2'; gather(+b2, relu, scale) -> h3' ----
    gemm_kernel<64, 32, 0, false, true><<<cdiv(N, B), B>>>(bufA, W2, nullptr, t2h, dinv, N);
    gatherS_kernel<32, true, true><<<cdiv((long long)N * 4, B), B>>>(t2h, h3h, csr, rowstart, deg, dinv, b2, N);

    // ---- layer 3: gather C=32 -> fp32 agg3; fused 32->32 relu GEMM + pooling ----
    gatherS_kernel<32, false, false><<<cdiv((long long)N * 4, B), B>>>(h3h, bufD, csr, rowstart, deg, dinv, nullptr, N);
    gemm3_pool_kernel<<<cdiv(N, B), B>>>(bufD, W3, b3, batch, gmax, gsum, gcnt, N);

    // ---- output head ----
    out_kernel<<<cdiv(N_GRAPHS_C * 10, B), B>>>(gmax, gsum, gcnt, Wout, bout, (float*)d_out);
}